// round 2
// baseline (speedup 1.0000x reference)
#include <cuda_runtime.h>
#include <cstdint>

// ============================================================================
// Problem constants
// ============================================================================
#define CCH   512
#define LSEQ  8192
#define NB    8
#define NPOS  (NB * LSEQ)          // 65536 positions
#define MTILE 128                  // out-channel tile
#define NTILE 256                  // position tile (divides LSEQ)
#define ICCH  32                   // in-channel chunk per stage
#define NSTAGES (CCH / ICCH)       // 16
#define NTHREADS 256
#define WSZ   (3 * 512 * 512)      // elems per weight tensor
#define TAPSZ (512 * 512)

// smem layout (bytes). Row stride 160B (40 floats) for bank-conflict-free frags.
#define ROWB       160
#define A_TAP_B    (128 * ROWB)            // 20480
#define A_BYTES    (3 * A_TAP_B)           // 61440
#define B_OFF      A_BYTES
#define B_ROWS     272                     // >= 256 + 2*dil(max 5)
#define B_BYTES    (B_ROWS * ROWB)         // 43520
#define STAGE_BYTES (A_BYTES + B_BYTES)    // 104960
#define SMEM_TOTAL (2 * STAGE_BYTES)       // 209920

// ============================================================================
// Scratch (__device__ globals — no allocations allowed)
// ============================================================================
__device__ float g_Xt[(size_t)NPOS * CCH];   // activations transposed [pos][c]
__device__ float g_H [(size_t)NPOS * CCH];   // branch intermediate
__device__ float g_Wp[6 * WSZ];              // ternary weights [w][tap][oc][ic]
__device__ float g_partial[6 * 32];
__device__ float g_scales[6];

// ============================================================================
// Helpers
// ============================================================================
__device__ __forceinline__ uint32_t smem_u32(const void* p) {
    uint32_t a;
    asm("{ .reg .u64 t; cvta.to.shared.u64 t, %1; cvt.u32.u64 %0, t; }" : "=r"(a) : "l"(p));
    return a;
}
__device__ __forceinline__ void cp_async16(uint32_t dst, const void* src, uint32_t srcsize) {
    asm volatile("cp.async.cg.shared.global [%0], [%1], 16, %2;"
                 :: "r"(dst), "l"(src), "r"(srcsize) : "memory");
}
__device__ __forceinline__ void cp_commit() {
    asm volatile("cp.async.commit_group;" ::: "memory");
}
__device__ __forceinline__ uint32_t f2tf32(uint32_t f) {
    uint32_t u;
    asm("cvt.rna.tf32.f32 %0, %1;" : "=r"(u) : "r"(f));
    return u;
}
__device__ __forceinline__ void lds_v2(uint32_t& x, uint32_t& y, uint32_t addr) {
    asm volatile("ld.shared.v2.b32 {%0, %1}, [%2];" : "=r"(x), "=r"(y) : "r"(addr));
}
__device__ __forceinline__ void mma_tf32(float& d0, float& d1, float& d2, float& d3,
                                         uint32_t a0, uint32_t a1, uint32_t a2, uint32_t a3,
                                         uint32_t b0, uint32_t b1) {
    asm volatile("mma.sync.aligned.m16n8k8.row.col.f32.tf32.tf32.f32 "
                 "{%0,%1,%2,%3}, {%4,%5,%6,%7}, {%8,%9}, {%0,%1,%2,%3};"
                 : "+f"(d0), "+f"(d1), "+f"(d2), "+f"(d3)
                 : "r"(a0), "r"(a1), "r"(a2), "r"(a3), "r"(b0), "r"(b1));
}

// ============================================================================
// Weight prep: scale = mean(|w|)+1e-5, ternary = clip(rint(w/scale),-1,1)
// Deterministic: fixed-order block partials + fixed-order finalize.
// ============================================================================
#define RCHUNK 24576  // 786432 / 32 blocks

__global__ void reduce_abs_kernel(const float* w0, const float* w1, const float* w2,
                                  const float* w3, const float* w4, const float* w5) {
    const float* ws[6] = {w0, w1, w2, w3, w4, w5};
    const float* w = ws[blockIdx.y];
    __shared__ float red[256];
    int n0 = blockIdx.x * RCHUNK;
    float s = 0.f;
    for (int i = threadIdx.x; i < RCHUNK; i += 256) s += fabsf(w[n0 + i]);
    red[threadIdx.x] = s;
    __syncthreads();
    for (int k = 128; k > 0; k >>= 1) {
        if (threadIdx.x < k) red[threadIdx.x] += red[threadIdx.x + k];
        __syncthreads();
    }
    if (threadIdx.x == 0) g_partial[blockIdx.y * 32 + blockIdx.x] = red[0];
}

__global__ void finalize_scale_kernel() {
    int t = threadIdx.x;
    if (t < 6) {
        float s = 0.f;
        for (int i = 0; i < 32; i++) s += g_partial[t * 32 + i];
        g_scales[t] = s / (float)WSZ + 1e-5f;
    }
}

// repack: Wp[w][tap][oc][ic] = clip(rint(w_in[oc][ic][tap]/scale), -1, 1)  (exact ternary)
__global__ void quant_kernel(const float* w0, const float* w1, const float* w2,
                             const float* w3, const float* w4, const float* w5) {
    const float* ws[6] = {w0, w1, w2, w3, w4, w5};
    int widx = blockIdx.y;
    int idx = blockIdx.x * 256 + threadIdx.x;   // [0, 786432)
    int k = idx / TAPSZ;
    int r = idx - k * TAPSZ;
    int o = r >> 9;
    int i = r & 511;
    float v = ws[widx][o * 1536 + i * 3 + k];
    float q = rintf(v / g_scales[widx]);
    q = fmaxf(-1.f, fminf(1.f, q));
    g_Wp[(size_t)widx * WSZ + (size_t)k * TAPSZ + o * 512 + i] = q;
}

// ============================================================================
// Transposes: x[B][C][L] <-> Xt[(b*L+l)][c]
// ============================================================================
__global__ void transpose_in_kernel(const float* __restrict__ x, float* __restrict__ xt) {
    __shared__ float tile[32][33];
    int l0 = blockIdx.x * 32, c0 = blockIdx.y * 32, bb = blockIdx.z;
    int tx = threadIdx.x, ty = threadIdx.y;
#pragma unroll
    for (int i = ty; i < 32; i += 8)
        tile[i][tx] = x[((size_t)(bb * CCH + c0 + i)) * LSEQ + l0 + tx];
    __syncthreads();
#pragma unroll
    for (int i = ty; i < 32; i += 8)
        xt[((size_t)(bb * LSEQ + l0 + i)) * CCH + c0 + tx] = tile[tx][i];
}

__global__ void transpose_out_kernel(const float* __restrict__ xt, float* __restrict__ out) {
    __shared__ float tile[32][33];
    int l0 = blockIdx.x * 32, c0 = blockIdx.y * 32, bb = blockIdx.z;
    int tx = threadIdx.x, ty = threadIdx.y;
#pragma unroll
    for (int i = ty; i < 32; i += 8)
        tile[i][tx] = xt[((size_t)(bb * LSEQ + l0 + i)) * CCH + c0 + tx];
    __syncthreads();
#pragma unroll
    for (int i = ty; i < 32; i += 8)
        out[((size_t)(bb * CCH + c0 + i)) * LSEQ + l0 + tx] = tile[tx][i];
}

// ============================================================================
// Conv kernel (implicit GEMM, mma.sync tf32):
//   Y[oc, pos] = scale * sum_tap sum_ic W[oc,ic,tap] * X[pos+(tap-1)*dil, ic] + bias[oc]
// mode 0: out[pos][oc] = lrelu(Y)
// mode 1: out[pos][oc] += Y   (residual)
// CTA: 128 oc x 256 pos, 8 warps of 64x64, K folded = 3 taps x 32 ic per stage.
// ============================================================================
__global__ void __launch_bounds__(NTHREADS, 1)
conv_kernel(const float* __restrict__ in, float* __restrict__ out,
            const float* __restrict__ bias, int widx, int dil, int mode) {
    extern __shared__ char smem[];
    const uint32_t sb = smem_u32(smem);

    const int tid  = threadIdx.x;
    const int lane = tid & 31;
    const int wid  = tid >> 5;
    const int warp_m = wid & 1;        // 0..1 -> oc halves of 64
    const int warp_n = wid >> 1;       // 0..3 -> pos quarters of 64

    const int oc0  = blockIdx.x * MTILE;
    const int pos0 = blockIdx.y * NTILE;
    const int bb   = pos0 >> 13;              // / LSEQ
    const int l0   = pos0 & (LSEQ - 1);

    const float* wbase = g_Wp + (size_t)widx * WSZ + (size_t)oc0 * CCH;
    const float* xbase = in + ((size_t)bb << 13) * CCH;

    const int nbrows  = NTILE + 2 * dil;          // extended B rows
    const int ncopies = 3072 + nbrows * 8;        // A: 3*128*8, B: nbrows*8 (16B each)

    // -------- stage loader (cp.async) --------
    auto load_stage = [&](int s, int buf) {
        const int ic0 = s * ICCH;
        const uint32_t sbuf = sb + buf * STAGE_BYTES;
        for (int t = tid; t < ncopies; t += NTHREADS) {
            if (t < 3072) {
                int tap = t >> 10, rem = t & 1023, row = rem >> 3, q = rem & 7;
                const float* src = wbase + (size_t)tap * TAPSZ + (size_t)row * CCH + ic0 + q * 4;
                cp_async16(sbuf + tap * A_TAP_B + row * ROWB + q * 16, src, 16);
            } else {
                int t2 = t - 3072;
                int row = t2 >> 3, q = t2 & 7;
                int l = l0 + row - dil;
                uint32_t ok = (l >= 0 && l < LSEQ) ? 16u : 0u;
                int lcl = min(max(l, 0), LSEQ - 1);
                const float* src = xbase + (size_t)lcl * CCH + ic0 + q * 4;
                cp_async16(sbuf + B_OFF + row * ROWB + q * 16, src, ok);
            }
        }
        cp_commit();
    };

    float acc[4][8][4];
#pragma unroll
    for (int mi = 0; mi < 4; mi++)
#pragma unroll
        for (int ni = 0; ni < 8; ni++)
#pragma unroll
            for (int r = 0; r < 4; r++) acc[mi][ni][r] = 0.f;

    load_stage(0, 0);

    const uint32_t col0 = 8u * (lane & 3);   // byte offset of (2c,2c+1) col pair
    const int rsub = lane >> 2;              // 0..7 row within fragment

#pragma unroll 1
    for (int s = 0; s < NSTAGES; ++s) {
        const int buf = s & 1;
        if (s + 1 < NSTAGES) load_stage(s + 1, buf ^ 1);
        if (s + 1 < NSTAGES) asm volatile("cp.async.wait_group 1;" ::: "memory");
        else                 asm volatile("cp.async.wait_group 0;" ::: "memory");
        __syncthreads();

        const uint32_t sbuf = sb + buf * STAGE_BYTES;
#pragma unroll
        for (int tap = 0; tap < 3; ++tap) {
            const uint32_t Ab = sbuf + tap * A_TAP_B + (warp_m * 64 + rsub) * ROWB;
            const uint32_t Bb = sbuf + B_OFF + (tap * dil + warp_n * 64 + rsub) * ROWB;
#pragma unroll
            for (int g = 0; g < 4; ++g) {
                const uint32_t coff = col0 + 32u * g;
                // A fragments: a0=(r, k=c) a2=(r, k=c+4) from cols (2c, 2c+1)
                uint32_t a[4][4];
#pragma unroll
                for (int mi = 0; mi < 4; mi++) {
                    uint32_t lo0, lo1, hi0, hi1;
                    lds_v2(lo0, lo1, Ab + mi * 16 * ROWB + coff);
                    lds_v2(hi0, hi1, Ab + (mi * 16 + 8) * ROWB + coff);
                    a[mi][0] = lo0; a[mi][1] = hi0; a[mi][2] = lo1; a[mi][3] = hi1;
                }
                // B fragments: b0=(k=c, n) b1=(k=c+4, n); tf32-round activations
                uint32_t b[8][2];
#pragma unroll
                for (int ni = 0; ni < 8; ni++) {
                    uint32_t x0, x1;
                    lds_v2(x0, x1, Bb + ni * 8 * ROWB + coff);
                    b[ni][0] = f2tf32(x0);
                    b[ni][1] = f2tf32(x1);
                }
#pragma unroll
                for (int mi = 0; mi < 4; mi++)
#pragma unroll
                    for (int ni = 0; ni < 8; ni++)
                        mma_tf32(acc[mi][ni][0], acc[mi][ni][1], acc[mi][ni][2], acc[mi][ni][3],
                                 a[mi][0], a[mi][1], a[mi][2], a[mi][3],
                                 b[ni][0], b[ni][1]);
            }
        }
        __syncthreads();
    }

    // -------- epilogue --------
    const float sc = g_scales[widx];
    if (mode == 0) {
#pragma unroll
        for (int mi = 0; mi < 4; mi++) {
            const int oc = oc0 + warp_m * 64 + mi * 16 + rsub;
            const float bv0 = bias[oc], bv1 = bias[oc + 8];
#pragma unroll
            for (int ni = 0; ni < 8; ni++) {
                const int pos = pos0 + warp_n * 64 + ni * 8 + 2 * (lane & 3);
                float* p0 = out + (size_t)pos * CCH + oc;
                float y;
                y = fmaf(sc, acc[mi][ni][0], bv0); p0[0]       = (y >= 0.f) ? y : 0.1f * y;
                y = fmaf(sc, acc[mi][ni][2], bv1); p0[8]       = (y >= 0.f) ? y : 0.1f * y;
                y = fmaf(sc, acc[mi][ni][1], bv0); p0[CCH]     = (y >= 0.f) ? y : 0.1f * y;
                y = fmaf(sc, acc[mi][ni][3], bv1); p0[CCH + 8] = (y >= 0.f) ? y : 0.1f * y;
            }
        }
    } else {
#pragma unroll
        for (int mi = 0; mi < 4; mi++) {
            const int oc = oc0 + warp_m * 64 + mi * 16 + rsub;
            const float bv0 = bias[oc], bv1 = bias[oc + 8];
#pragma unroll
            for (int ni = 0; ni < 8; ni++) {
                const int pos = pos0 + warp_n * 64 + ni * 8 + 2 * (lane & 3);
                float* p0 = out + (size_t)pos * CCH + oc;
                p0[0]       += fmaf(sc, acc[mi][ni][0], bv0);
                p0[8]       += fmaf(sc, acc[mi][ni][2], bv1);
                p0[CCH]     += fmaf(sc, acc[mi][ni][1], bv0);
                p0[CCH + 8] += fmaf(sc, acc[mi][ni][3], bv1);
            }
        }
    }
}

// ============================================================================
// Launch
// ============================================================================
extern "C" void kernel_launch(void* const* d_in, const int* in_sizes, int n_in,
                              void* d_out, int out_size) {
    (void)in_sizes; (void)n_in; (void)out_size;
    const float* x = (const float*)d_in[0];
    const float* w[6];
    const float* b[6];
    for (int br = 0; br < 3; br++)
        for (int j = 0; j < 2; j++) {
            w[br * 2 + j] = (const float*)d_in[1 + 4 * br + 2 * j];
            b[br * 2 + j] = (const float*)d_in[2 + 4 * br + 2 * j];
        }

    float *Xt, *H;
    cudaGetSymbolAddress((void**)&Xt, g_Xt);
    cudaGetSymbolAddress((void**)&H, g_H);
    cudaFuncSetAttribute(conv_kernel, cudaFuncAttributeMaxDynamicSharedMemorySize, SMEM_TOTAL);

    // weight prep (deterministic)
    reduce_abs_kernel<<<dim3(32, 6), 256>>>(w[0], w[1], w[2], w[3], w[4], w[5]);
    finalize_scale_kernel<<<1, 32>>>();
    quant_kernel<<<dim3(WSZ / 256, 6), 256>>>(w[0], w[1], w[2], w[3], w[4], w[5]);

    // transpose in
    transpose_in_kernel<<<dim3(LSEQ / 32, CCH / 32, NB), dim3(32, 8)>>>(x, Xt);

    const int dils[3] = {1, 3, 5};
    for (int br = 0; br < 3; br++) {
        conv_kernel<<<dim3(CCH / MTILE, NPOS / NTILE), NTHREADS, SMEM_TOTAL>>>(
            Xt, H, b[2 * br], 2 * br, dils[br], 0);
        conv_kernel<<<dim3(CCH / MTILE, NPOS / NTILE), NTHREADS, SMEM_TOTAL>>>(
            H, Xt, b[2 * br + 1], 2 * br + 1, 1, 1);
    }

    // transpose out
    transpose_out_kernel<<<dim3(LSEQ / 32, CCH / 32, NB), dim3(32, 8)>>>(Xt, (float*)d_out);
}

// round 3
// speedup vs baseline: 1.5899x; 1.5899x over previous
#include <cuda_runtime.h>
#include <cuda_fp16.h>
#include <cstdint>

// ============================================================================
// Problem constants
// ============================================================================
#define CCH   512
#define LSEQ  8192
#define NB    8
#define NPOS  (NB * LSEQ)          // 65536 positions
#define MTILE 256                  // position tile (M)
#define NTILE 128                  // out-channel tile (N)
#define ICCH  32                   // in-channel chunk per stage
#define NSTAGES (CCH / ICCH)       // 16
#define NTHREADS 256
#define WSZ   (3 * 512 * 512)
#define TAPSZ (512 * 512)

// smem layout (fp16): W tiles then X tiles. Row = 32 ic * 2B = 64B.
#define ROWB        64
#define W_TAP_B     (128 * ROWB)           // 8192
#define W_BYTES     (3 * W_TAP_B)          // 24576
#define X_OFF       W_BYTES
#define X_ROWS      272                    // >= 256 + 2*5
#define X_BYTES     (X_ROWS * ROWB)        // 17408
#define STAGE_BYTES (W_BYTES + X_BYTES)    // 41984
#define SMEM_TOTAL  (2 * STAGE_BYTES)      // 83968

// ============================================================================
// Scratch (__device__ globals — no allocations allowed)
// ============================================================================
__device__ __half g_Xt16[(size_t)NPOS * CCH];   // fp16 mirror of residual stream
__device__ __half g_H16 [(size_t)NPOS * CCH];   // branch intermediate (fp16)
__device__ float  g_Xres[(size_t)NPOS * CCH];   // fp32 residual truth [pos][c]
__device__ __half g_Wp16[6 * WSZ];              // ternary weights fp16 [w][tap][oc][ic]
__device__ float  g_partial[6 * 32];
__device__ float  g_scales[6];

// ============================================================================
// Helpers
// ============================================================================
__device__ __forceinline__ uint32_t smem_u32(const void* p) {
    uint32_t a;
    asm("{ .reg .u64 t; cvta.to.shared.u64 t, %1; cvt.u32.u64 %0, t; }" : "=r"(a) : "l"(p));
    return a;
}
__device__ __forceinline__ void cp_async16(uint32_t dst, const void* src, uint32_t srcsize) {
    asm volatile("cp.async.cg.shared.global [%0], [%1], 16, %2;"
                 :: "r"(dst), "l"(src), "r"(srcsize) : "memory");
}
__device__ __forceinline__ void cp_commit() {
    asm volatile("cp.async.commit_group;" ::: "memory");
}
__device__ __forceinline__ void lds_v4(uint32_t* r, uint32_t addr) {
    asm volatile("ld.shared.v4.b32 {%0,%1,%2,%3}, [%4];"
                 : "=r"(r[0]), "=r"(r[1]), "=r"(r[2]), "=r"(r[3]) : "r"(addr));
}
// D[16x8 f32] += A[16x16 f16] * B[16x8 f16]  (A row-major=activations, B col-major=weights)
__device__ __forceinline__ void mma_f16(float& d0, float& d1, float& d2, float& d3,
                                        uint32_t a0, uint32_t a1, uint32_t a2, uint32_t a3,
                                        uint32_t b0, uint32_t b1) {
    asm volatile("mma.sync.aligned.m16n8k16.row.col.f32.f16.f16.f32 "
                 "{%0,%1,%2,%3}, {%4,%5,%6,%7}, {%8,%9}, {%0,%1,%2,%3};"
                 : "+f"(d0), "+f"(d1), "+f"(d2), "+f"(d3)
                 : "r"(a0), "r"(a1), "r"(a2), "r"(a3), "r"(b0), "r"(b1));
}

// ============================================================================
// Weight prep: scale = mean(|w|)+1e-5, ternary = clip(rint(w/scale),-1,1)
// ============================================================================
#define RCHUNK 24576

__global__ void reduce_abs_kernel(const float* w0, const float* w1, const float* w2,
                                  const float* w3, const float* w4, const float* w5) {
    const float* ws[6] = {w0, w1, w2, w3, w4, w5};
    const float* w = ws[blockIdx.y];
    __shared__ float red[256];
    int n0 = blockIdx.x * RCHUNK;
    float s = 0.f;
    for (int i = threadIdx.x; i < RCHUNK; i += 256) s += fabsf(w[n0 + i]);
    red[threadIdx.x] = s;
    __syncthreads();
    for (int k = 128; k > 0; k >>= 1) {
        if (threadIdx.x < k) red[threadIdx.x] += red[threadIdx.x + k];
        __syncthreads();
    }
    if (threadIdx.x == 0) g_partial[blockIdx.y * 32 + blockIdx.x] = red[0];
}

__global__ void finalize_scale_kernel() {
    int t = threadIdx.x;
    if (t < 6) {
        float s = 0.f;
        for (int i = 0; i < 32; i++) s += g_partial[t * 32 + i];
        g_scales[t] = s / (float)WSZ + 1e-5f;
    }
}

// Wp16[w][tap][oc][ic] = clip(rint(w_in[oc][ic][tap]/scale), -1, 1)  (exact in fp16)
__global__ void quant_kernel(const float* w0, const float* w1, const float* w2,
                             const float* w3, const float* w4, const float* w5) {
    const float* ws[6] = {w0, w1, w2, w3, w4, w5};
    int widx = blockIdx.y;
    int idx = blockIdx.x * 256 + threadIdx.x;
    int k = idx / TAPSZ;
    int r = idx - k * TAPSZ;
    int o = r >> 9;
    int i = r & 511;
    float v = ws[widx][o * 1536 + i * 3 + k];
    float q = rintf(v / g_scales[widx]);
    q = fmaxf(-1.f, fminf(1.f, q));
    g_Wp16[(size_t)widx * WSZ + (size_t)k * TAPSZ + o * 512 + i] = __float2half_rn(q);
}

// ============================================================================
// Transposes
// ============================================================================
__global__ void transpose_in_kernel(const float* __restrict__ x,
                                    __half* __restrict__ xt16, float* __restrict__ xres) {
    __shared__ float tile[32][33];
    int l0 = blockIdx.x * 32, c0 = blockIdx.y * 32, bb = blockIdx.z;
    int tx = threadIdx.x, ty = threadIdx.y;
#pragma unroll
    for (int i = ty; i < 32; i += 8)
        tile[i][tx] = x[((size_t)(bb * CCH + c0 + i)) * LSEQ + l0 + tx];
    __syncthreads();
#pragma unroll
    for (int i = ty; i < 32; i += 8) {
        float v = tile[tx][i];
        size_t idx = ((size_t)(bb * LSEQ + l0 + i)) * CCH + c0 + tx;
        xt16[idx] = __float2half_rn(v);
        xres[idx] = v;
    }
}

__global__ void transpose_out_kernel(const float* __restrict__ xres, float* __restrict__ out) {
    __shared__ float tile[32][33];
    int l0 = blockIdx.x * 32, c0 = blockIdx.y * 32, bb = blockIdx.z;
    int tx = threadIdx.x, ty = threadIdx.y;
#pragma unroll
    for (int i = ty; i < 32; i += 8)
        tile[i][tx] = xres[((size_t)(bb * LSEQ + l0 + i)) * CCH + c0 + tx];
    __syncthreads();
#pragma unroll
    for (int i = ty; i < 32; i += 8)
        out[((size_t)(bb * CCH + c0 + i)) * LSEQ + l0 + tx] = tile[tx][i];
}

// ============================================================================
// Conv kernel (implicit GEMM, fp16 mma.sync, fp32 acc):
//   Y[pos, oc] = scale * sum_tap sum_ic X[pos+(tap-1)*dil, ic] * W[oc,ic,tap] + bias[oc]
// mode 0: H16[pos][oc] = lrelu(Y)
// mode 1: res += Y (fp32), Xt16 = fp16(res)
// CTA: 256 pos (M) x 128 oc (N); 8 warps of 64x64.
// ============================================================================
__global__ void __launch_bounds__(NTHREADS, 1)
conv_kernel(const __half* __restrict__ in, __half* __restrict__ out16,
            float* __restrict__ res, __half* __restrict__ res16,
            const float* __restrict__ bias, int widx, int dil, int mode) {
    extern __shared__ char smem[];
    const uint32_t sb = smem_u32(smem);

    const int tid  = threadIdx.x;
    const int lane = tid & 31;
    const int wid  = tid >> 5;
    const int warp_p = wid & 3;        // 4 x 64-pos
    const int warp_o = wid >> 2;       // 2 x 64-oc

    const int pos0 = blockIdx.y * MTILE;
    const int oc0  = blockIdx.x * NTILE;
    const int bb   = pos0 >> 13;
    const int l0   = pos0 & (LSEQ - 1);

    const __half* wbase = g_Wp16 + (size_t)widx * WSZ;
    const __half* xbase = in + ((size_t)bb << 13) * CCH;

    // -------- stage loader (cp.async, 16B = 8 halves) --------
    // W: 3*128*4 = 1536 chunks, X: 272*4 = 1088 chunks
    auto load_stage = [&](int s, int buf) {
        const int ic0 = s * ICCH;
        const uint32_t sbuf = sb + buf * STAGE_BYTES;
        for (int t = tid; t < 2624; t += NTHREADS) {
            if (t < 1536) {
                int tap = t >> 9, rem = t & 511, row = rem >> 2, q = rem & 3;
                const __half* src = wbase + (size_t)tap * TAPSZ + (size_t)(oc0 + row) * CCH + ic0 + q * 8;
                cp_async16(sbuf + tap * W_TAP_B + row * ROWB + q * 16, src, 16);
            } else {
                int t2 = t - 1536;
                int row = t2 >> 2, q = t2 & 3;
                int l = l0 + row - dil;
                uint32_t ok = (l >= 0 && l < LSEQ) ? 16u : 0u;
                int lcl = min(max(l, 0), LSEQ - 1);
                const __half* src = xbase + (size_t)lcl * CCH + ic0 + q * 8;
                cp_async16(sbuf + X_OFF + row * ROWB + q * 16, src, ok);
            }
        }
        cp_commit();
    };

    float acc[4][8][4];
#pragma unroll
    for (int mi = 0; mi < 4; mi++)
#pragma unroll
        for (int ni = 0; ni < 8; ni++)
#pragma unroll
            for (int r = 0; r < 4; r++) acc[mi][ni][r] = 0.f;

    load_stage(0, 0);

    const int rsub = lane >> 2;               // fragment row within 8
    const uint32_t coff = 16u * (lane & 3);   // 16B unit = ic 8c..8c+7

#pragma unroll 1
    for (int s = 0; s < NSTAGES; ++s) {
        const int buf = s & 1;
        if (s + 1 < NSTAGES) {
            load_stage(s + 1, buf ^ 1);
            asm volatile("cp.async.wait_group 1;" ::: "memory");
        } else {
            asm volatile("cp.async.wait_group 0;" ::: "memory");
        }
        __syncthreads();

        const uint32_t sbuf = sb + buf * STAGE_BYTES;
#pragma unroll
        for (int tap = 0; tap < 3; ++tap) {
            // B operand (weights): 8 ni fragments, both k-groups in one v4
            uint32_t wf[8][4];
            const uint32_t Wb = sbuf + tap * W_TAP_B + (warp_o * 64 + rsub) * ROWB + coff;
#pragma unroll
            for (int ni = 0; ni < 8; ni++) lds_v4(wf[ni], Wb + ni * 8 * ROWB);

            const uint32_t Xb = sbuf + X_OFF + (tap * dil + warp_p * 64 + rsub) * ROWB + coff;
#pragma unroll
            for (int mi = 0; mi < 4; mi++) {
                uint32_t ua[4], ub[4];
                lds_v4(ua, Xb + mi * 16 * ROWB);
                lds_v4(ub, Xb + (mi * 16 + 8) * ROWB);
#pragma unroll
                for (int ni = 0; ni < 8; ni++) {
                    mma_f16(acc[mi][ni][0], acc[mi][ni][1], acc[mi][ni][2], acc[mi][ni][3],
                            ua[0], ub[0], ua[1], ub[1], wf[ni][0], wf[ni][1]);
                    mma_f16(acc[mi][ni][0], acc[mi][ni][1], acc[mi][ni][2], acc[mi][ni][3],
                            ua[2], ub[2], ua[3], ub[3], wf[ni][2], wf[ni][3]);
                }
            }
        }
        __syncthreads();
    }

    // -------- epilogue --------
    // acc c0=(pos r, oc 2c), c1=(pos r, oc 2c+1), c2=(pos r+8, ...), c3
    const float sc = g_scales[widx];
    const int pbase = pos0 + warp_p * 64 + rsub;
    const int obase = oc0 + warp_o * 64 + 2 * (lane & 3);
#pragma unroll
    for (int ni = 0; ni < 8; ni++) {
        const int oc = obase + ni * 8;
        const float2 bv = *reinterpret_cast<const float2*>(bias + oc);
#pragma unroll
        for (int mi = 0; mi < 4; mi++) {
            const int pos = pbase + mi * 16;
            float y0 = fmaf(sc, acc[mi][ni][0], bv.x);
            float y1 = fmaf(sc, acc[mi][ni][1], bv.y);
            float y2 = fmaf(sc, acc[mi][ni][2], bv.x);
            float y3 = fmaf(sc, acc[mi][ni][3], bv.y);
            if (mode == 0) {
                y0 = (y0 >= 0.f) ? y0 : 0.1f * y0;
                y1 = (y1 >= 0.f) ? y1 : 0.1f * y1;
                y2 = (y2 >= 0.f) ? y2 : 0.1f * y2;
                y3 = (y3 >= 0.f) ? y3 : 0.1f * y3;
                *reinterpret_cast<__half2*>(out16 + (size_t)pos * CCH + oc) =
                    __floats2half2_rn(y0, y1);
                *reinterpret_cast<__half2*>(out16 + (size_t)(pos + 8) * CCH + oc) =
                    __floats2half2_rn(y2, y3);
            } else {
                float2* rp0 = reinterpret_cast<float2*>(res + (size_t)pos * CCH + oc);
                float2 r0 = *rp0;
                r0.x += y0; r0.y += y1;
                *rp0 = r0;
                *reinterpret_cast<__half2*>(res16 + (size_t)pos * CCH + oc) =
                    __floats2half2_rn(r0.x, r0.y);
                float2* rp1 = reinterpret_cast<float2*>(res + (size_t)(pos + 8) * CCH + oc);
                float2 r1 = *rp1;
                r1.x += y2; r1.y += y3;
                *rp1 = r1;
                *reinterpret_cast<__half2*>(res16 + (size_t)(pos + 8) * CCH + oc) =
                    __floats2half2_rn(r1.x, r1.y);
            }
        }
    }
}

// ============================================================================
// Launch
// ============================================================================
extern "C" void kernel_launch(void* const* d_in, const int* in_sizes, int n_in,
                              void* d_out, int out_size) {
    (void)in_sizes; (void)n_in; (void)out_size;
    const float* x = (const float*)d_in[0];
    const float* w[6];
    const float* b[6];
    for (int br = 0; br < 3; br++)
        for (int j = 0; j < 2; j++) {
            w[br * 2 + j] = (const float*)d_in[1 + 4 * br + 2 * j];
            b[br * 2 + j] = (const float*)d_in[2 + 4 * br + 2 * j];
        }

    __half *Xt16, *H16;
    float *Xres;
    cudaGetSymbolAddress((void**)&Xt16, g_Xt16);
    cudaGetSymbolAddress((void**)&H16, g_H16);
    cudaGetSymbolAddress((void**)&Xres, g_Xres);
    cudaFuncSetAttribute(conv_kernel, cudaFuncAttributeMaxDynamicSharedMemorySize, SMEM_TOTAL);

    // weight prep (deterministic)
    reduce_abs_kernel<<<dim3(32, 6), 256>>>(w[0], w[1], w[2], w[3], w[4], w[5]);
    finalize_scale_kernel<<<1, 32>>>();
    quant_kernel<<<dim3(WSZ / 256, 6), 256>>>(w[0], w[1], w[2], w[3], w[4], w[5]);

    // transpose in: fp16 mirror + fp32 residual
    transpose_in_kernel<<<dim3(LSEQ / 32, CCH / 32, NB), dim3(32, 8)>>>(x, Xt16, Xres);

    const int dils[3] = {1, 3, 5};
    for (int br = 0; br < 3; br++) {
        // conv A (dilated) -> lrelu -> H16
        conv_kernel<<<dim3(CCH / NTILE, NPOS / MTILE), NTHREADS, SMEM_TOTAL>>>(
            Xt16, H16, nullptr, nullptr, b[2 * br], 2 * br, dils[br], 0);
        // conv B (dense) -> residual add into Xres (+fp16 mirror)
        conv_kernel<<<dim3(CCH / NTILE, NPOS / MTILE), NTHREADS, SMEM_TOTAL>>>(
            H16, nullptr, Xres, Xt16, b[2 * br + 1], 2 * br + 1, 1, 1);
    }

    // transpose out
    transpose_out_kernel<<<dim3(LSEQ / 32, CCH / 32, NB), dim3(32, 8)>>>(Xres, (float*)d_out);
}

// round 4
// speedup vs baseline: 1.5976x; 1.0049x over previous
#include <cuda_runtime.h>
#include <cuda_fp16.h>
#include <cstdint>

// ============================================================================
// Problem constants
// ============================================================================
#define CCH   512
#define LSEQ  8192
#define NB    8
#define NPOS  (NB * LSEQ)          // 65536 positions
#define MTILE 256                  // position tile (M)
#define NTILE 128                  // out-channel tile (N)
#define ICCH  32                   // in-channel chunk per stage
#define NSTAGES (CCH / ICCH)       // 16
#define NTHREADS 512
#define NBUF  3
#define WSZ   (3 * 512 * 512)
#define TAPSZ (512 * 512)

// smem layout (fp16): W tiles then X tiles. Row = 32 ic * 2B = 64B.
#define ROWB        64
#define W_TAP_B     (128 * ROWB)           // 8192
#define W_BYTES     (3 * W_TAP_B)          // 24576
#define X_OFF       W_BYTES
#define X_ROWS      272                    // >= 256 + 2*5
#define X_BYTES     (X_ROWS * ROWB)        // 17408
#define STAGE_BYTES (W_BYTES + X_BYTES)    // 41984
#define SMEM_TOTAL  (NBUF * STAGE_BYTES)   // 125952

// ============================================================================
// Scratch (__device__ globals — no allocations allowed)
// ============================================================================
__device__ __half g_Xt16[(size_t)NPOS * CCH];   // fp16 mirror of residual stream
__device__ __half g_H16 [(size_t)NPOS * CCH];   // branch intermediate (fp16)
__device__ float  g_Xres[(size_t)NPOS * CCH];   // fp32 residual truth [pos][c]
__device__ __half g_Wp16[6 * WSZ];              // ternary weights fp16 [w][tap][oc][ic]
__device__ float  g_partial[6 * 32];
__device__ float  g_scales[6];

// ============================================================================
// Helpers
// ============================================================================
__device__ __forceinline__ uint32_t smem_u32(const void* p) {
    uint32_t a;
    asm("{ .reg .u64 t; cvta.to.shared.u64 t, %1; cvt.u32.u64 %0, t; }" : "=r"(a) : "l"(p));
    return a;
}
__device__ __forceinline__ void cp_async16(uint32_t dst, const void* src, uint32_t srcsize) {
    asm volatile("cp.async.cg.shared.global [%0], [%1], 16, %2;"
                 :: "r"(dst), "l"(src), "r"(srcsize) : "memory");
}
__device__ __forceinline__ void cp_commit() {
    asm volatile("cp.async.commit_group;" ::: "memory");
}
__device__ __forceinline__ void lds_v4(uint32_t* r, uint32_t addr) {
    asm volatile("ld.shared.v4.b32 {%0,%1,%2,%3}, [%4];"
                 : "=r"(r[0]), "=r"(r[1]), "=r"(r[2]), "=r"(r[3]) : "r"(addr));
}
// D[16x8 f32] += A[16x16 f16] * B[16x8 f16]
__device__ __forceinline__ void mma_f16(float& d0, float& d1, float& d2, float& d3,
                                        uint32_t a0, uint32_t a1, uint32_t a2, uint32_t a3,
                                        uint32_t b0, uint32_t b1) {
    asm volatile("mma.sync.aligned.m16n8k16.row.col.f32.f16.f16.f32 "
                 "{%0,%1,%2,%3}, {%4,%5,%6,%7}, {%8,%9}, {%0,%1,%2,%3};"
                 : "+f"(d0), "+f"(d1), "+f"(d2), "+f"(d3)
                 : "r"(a0), "r"(a1), "r"(a2), "r"(a3), "r"(b0), "r"(b1));
}

// ============================================================================
// Weight prep: scale = mean(|w|)+1e-5, ternary = clip(rint(w/scale),-1,1)
// ============================================================================
#define RCHUNK 24576

__global__ void reduce_abs_kernel(const float* w0, const float* w1, const float* w2,
                                  const float* w3, const float* w4, const float* w5) {
    const float* ws[6] = {w0, w1, w2, w3, w4, w5};
    const float* w = ws[blockIdx.y];
    __shared__ float red[256];
    int n0 = blockIdx.x * RCHUNK;
    float s = 0.f;
    for (int i = threadIdx.x; i < RCHUNK; i += 256) s += fabsf(w[n0 + i]);
    red[threadIdx.x] = s;
    __syncthreads();
    for (int k = 128; k > 0; k >>= 1) {
        if (threadIdx.x < k) red[threadIdx.x] += red[threadIdx.x + k];
        __syncthreads();
    }
    if (threadIdx.x == 0) g_partial[blockIdx.y * 32 + blockIdx.x] = red[0];
}

__global__ void finalize_scale_kernel() {
    int t = threadIdx.x;
    if (t < 6) {
        float s = 0.f;
        for (int i = 0; i < 32; i++) s += g_partial[t * 32 + i];
        g_scales[t] = s / (float)WSZ + 1e-5f;
    }
}

__global__ void quant_kernel(const float* w0, const float* w1, const float* w2,
                             const float* w3, const float* w4, const float* w5) {
    const float* ws[6] = {w0, w1, w2, w3, w4, w5};
    int widx = blockIdx.y;
    int idx = blockIdx.x * 256 + threadIdx.x;
    int k = idx / TAPSZ;
    int r = idx - k * TAPSZ;
    int o = r >> 9;
    int i = r & 511;
    float v = ws[widx][o * 1536 + i * 3 + k];
    float q = rintf(v / g_scales[widx]);
    q = fmaxf(-1.f, fminf(1.f, q));
    g_Wp16[(size_t)widx * WSZ + (size_t)k * TAPSZ + o * 512 + i] = __float2half_rn(q);
}

// ============================================================================
// Transposes
// ============================================================================
__global__ void transpose_in_kernel(const float* __restrict__ x,
                                    __half* __restrict__ xt16, float* __restrict__ xres) {
    __shared__ float tile[32][33];
    int l0 = blockIdx.x * 32, c0 = blockIdx.y * 32, bb = blockIdx.z;
    int tx = threadIdx.x, ty = threadIdx.y;
#pragma unroll
    for (int i = ty; i < 32; i += 8)
        tile[i][tx] = x[((size_t)(bb * CCH + c0 + i)) * LSEQ + l0 + tx];
    __syncthreads();
#pragma unroll
    for (int i = ty; i < 32; i += 8) {
        float v = tile[tx][i];
        size_t idx = ((size_t)(bb * LSEQ + l0 + i)) * CCH + c0 + tx;
        xt16[idx] = __float2half_rn(v);
        xres[idx] = v;
    }
}

__global__ void transpose_out_kernel(const float* __restrict__ xres, float* __restrict__ out) {
    __shared__ float tile[32][33];
    int l0 = blockIdx.x * 32, c0 = blockIdx.y * 32, bb = blockIdx.z;
    int tx = threadIdx.x, ty = threadIdx.y;
#pragma unroll
    for (int i = ty; i < 32; i += 8)
        tile[i][tx] = xres[((size_t)(bb * LSEQ + l0 + i)) * CCH + c0 + tx];
    __syncthreads();
#pragma unroll
    for (int i = ty; i < 32; i += 8)
        out[((size_t)(bb * CCH + c0 + i)) * LSEQ + l0 + tx] = tile[tx][i];
}

// ============================================================================
// Conv kernel (implicit GEMM, fp16 mma.sync, fp32 acc):
//   Y[pos, oc] = scale * sum_tap sum_ic X[pos+(tap-1)*dil, ic] * W[oc,ic,tap] + bias[oc]
// mode 0: H16 = lrelu(Y);  mode 1: res += Y (fp32), res16 = fp16(res)
// CTA: 256 pos x 128 oc; 16 warps of 64 pos x 32 oc; 3-stage cp.async pipeline.
// ============================================================================
__global__ void __launch_bounds__(NTHREADS, 1)
conv_kernel(const __half* __restrict__ in, __half* __restrict__ out16,
            float* __restrict__ res, __half* __restrict__ res16,
            const float* __restrict__ bias, int widx, int dil, int mode) {
    extern __shared__ char smem[];
    const uint32_t sb = smem_u32(smem);

    const int tid  = threadIdx.x;
    const int lane = tid & 31;
    const int wid  = tid >> 5;
    const int warp_p = wid & 3;        // 4 x 64-pos
    const int warp_o = wid >> 2;       // 4 x 32-oc

    const int pos0 = blockIdx.y * MTILE;
    const int oc0  = blockIdx.x * NTILE;
    const int bb   = pos0 >> 13;
    const int l0   = pos0 & (LSEQ - 1);

    const __half* wbase = g_Wp16 + (size_t)widx * WSZ;
    const __half* xbase = in + ((size_t)bb << 13) * CCH;

    // -------- stage loader (cp.async, 16B = 8 halves) --------
    auto load_stage = [&](int s, int buf) {
        const int ic0 = s * ICCH;
        const uint32_t sbuf = sb + buf * STAGE_BYTES;
        for (int t = tid; t < 2624; t += NTHREADS) {
            if (t < 1536) {
                int tap = t >> 9, rem = t & 511, row = rem >> 2, q = rem & 3;
                const __half* src = wbase + (size_t)tap * TAPSZ + (size_t)(oc0 + row) * CCH + ic0 + q * 8;
                cp_async16(sbuf + tap * W_TAP_B + row * ROWB + q * 16, src, 16);
            } else {
                int t2 = t - 1536;
                int row = t2 >> 2, q = t2 & 3;
                int l = l0 + row - dil;
                uint32_t ok = (l >= 0 && l < LSEQ) ? 16u : 0u;
                int lcl = min(max(l, 0), LSEQ - 1);
                const __half* src = xbase + (size_t)lcl * CCH + ic0 + q * 8;
                cp_async16(sbuf + X_OFF + row * ROWB + q * 16, src, ok);
            }
        }
        cp_commit();
    };

    float acc[4][4][4];
#pragma unroll
    for (int mi = 0; mi < 4; mi++)
#pragma unroll
        for (int ni = 0; ni < 4; ni++)
#pragma unroll
            for (int r = 0; r < 4; r++) acc[mi][ni][r] = 0.f;

    load_stage(0, 0);
    load_stage(1, 1);

    const int rsub = lane >> 2;               // fragment row within 8
    const uint32_t coff = 16u * (lane & 3);   // 16B unit = ic 8c..8c+7

#pragma unroll 1
    for (int s = 0; s < NSTAGES; ++s) {
        const int buf = s % NBUF;
        if (s + 2 < NSTAGES) {
            load_stage(s + 2, (s + 2) % NBUF);
            asm volatile("cp.async.wait_group 2;" ::: "memory");
        } else if (s + 1 < NSTAGES) {
            asm volatile("cp.async.wait_group 1;" ::: "memory");
        } else {
            asm volatile("cp.async.wait_group 0;" ::: "memory");
        }
        __syncthreads();

        const uint32_t sbuf = sb + buf * STAGE_BYTES;
#pragma unroll
        for (int tap = 0; tap < 3; ++tap) {
            uint32_t wf[4][4];
            const uint32_t Wb = sbuf + tap * W_TAP_B + (warp_o * 32 + rsub) * ROWB + coff;
#pragma unroll
            for (int ni = 0; ni < 4; ni++) lds_v4(wf[ni], Wb + ni * 8 * ROWB);

            const uint32_t Xb = sbuf + X_OFF + (tap * dil + warp_p * 64 + rsub) * ROWB + coff;
#pragma unroll
            for (int mi = 0; mi < 4; mi++) {
                uint32_t ua[4], ub[4];
                lds_v4(ua, Xb + mi * 16 * ROWB);
                lds_v4(ub, Xb + (mi * 16 + 8) * ROWB);
#pragma unroll
                for (int ni = 0; ni < 4; ni++) {
                    mma_f16(acc[mi][ni][0], acc[mi][ni][1], acc[mi][ni][2], acc[mi][ni][3],
                            ua[0], ub[0], ua[1], ub[1], wf[ni][0], wf[ni][1]);
                    mma_f16(acc[mi][ni][0], acc[mi][ni][1], acc[mi][ni][2], acc[mi][ni][3],
                            ua[2], ub[2], ua[3], ub[3], wf[ni][2], wf[ni][3]);
                }
            }
        }
        __syncthreads();
    }

    // -------- epilogue --------
    const float sc = g_scales[widx];
    const int pbase = pos0 + warp_p * 64 + rsub;
    const int obase = oc0 + warp_o * 32 + 2 * (lane & 3);
#pragma unroll
    for (int ni = 0; ni < 4; ni++) {
        const int oc = obase + ni * 8;
        const float2 bv = *reinterpret_cast<const float2*>(bias + oc);
#pragma unroll
        for (int mi = 0; mi < 4; mi++) {
            const int pos = pbase + mi * 16;
            float y0 = fmaf(sc, acc[mi][ni][0], bv.x);
            float y1 = fmaf(sc, acc[mi][ni][1], bv.y);
            float y2 = fmaf(sc, acc[mi][ni][2], bv.x);
            float y3 = fmaf(sc, acc[mi][ni][3], bv.y);
            if (mode == 0) {
                y0 = (y0 >= 0.f) ? y0 : 0.1f * y0;
                y1 = (y1 >= 0.f) ? y1 : 0.1f * y1;
                y2 = (y2 >= 0.f) ? y2 : 0.1f * y2;
                y3 = (y3 >= 0.f) ? y3 : 0.1f * y3;
                *reinterpret_cast<__half2*>(out16 + (size_t)pos * CCH + oc) =
                    __floats2half2_rn(y0, y1);
                *reinterpret_cast<__half2*>(out16 + (size_t)(pos + 8) * CCH + oc) =
                    __floats2half2_rn(y2, y3);
            } else {
                float2* rp0 = reinterpret_cast<float2*>(res + (size_t)pos * CCH + oc);
                float2 r0 = *rp0;
                r0.x += y0; r0.y += y1;
                *rp0 = r0;
                *reinterpret_cast<__half2*>(res16 + (size_t)pos * CCH + oc) =
                    __floats2half2_rn(r0.x, r0.y);
                float2* rp1 = reinterpret_cast<float2*>(res + (size_t)(pos + 8) * CCH + oc);
                float2 r1 = *rp1;
                r1.x += y2; r1.y += y3;
                *rp1 = r1;
                *reinterpret_cast<__half2*>(res16 + (size_t)(pos + 8) * CCH + oc) =
                    __floats2half2_rn(r1.x, r1.y);
            }
        }
    }
}

// ============================================================================
// Launch
// ============================================================================
extern "C" void kernel_launch(void* const* d_in, const int* in_sizes, int n_in,
                              void* d_out, int out_size) {
    (void)in_sizes; (void)n_in; (void)out_size;
    const float* x = (const float*)d_in[0];
    const float* w[6];
    const float* b[6];
    for (int br = 0; br < 3; br++)
        for (int j = 0; j < 2; j++) {
            w[br * 2 + j] = (const float*)d_in[1 + 4 * br + 2 * j];
            b[br * 2 + j] = (const float*)d_in[2 + 4 * br + 2 * j];
        }

    __half *Xt16, *H16;
    float *Xres;
    cudaGetSymbolAddress((void**)&Xt16, g_Xt16);
    cudaGetSymbolAddress((void**)&H16, g_H16);
    cudaGetSymbolAddress((void**)&Xres, g_Xres);
    cudaFuncSetAttribute(conv_kernel, cudaFuncAttributeMaxDynamicSharedMemorySize, SMEM_TOTAL);

    reduce_abs_kernel<<<dim3(32, 6), 256>>>(w[0], w[1], w[2], w[3], w[4], w[5]);
    finalize_scale_kernel<<<1, 32>>>();
    quant_kernel<<<dim3(WSZ / 256, 6), 256>>>(w[0], w[1], w[2], w[3], w[4], w[5]);

    transpose_in_kernel<<<dim3(LSEQ / 32, CCH / 32, NB), dim3(32, 8)>>>(x, Xt16, Xres);

    const int dils[3] = {1, 3, 5};
    for (int br = 0; br < 3; br++) {
        conv_kernel<<<dim3(CCH / NTILE, NPOS / MTILE), NTHREADS, SMEM_TOTAL>>>(
            Xt16, H16, nullptr, nullptr, b[2 * br], 2 * br, dils[br], 0);
        conv_kernel<<<dim3(CCH / NTILE, NPOS / MTILE), NTHREADS, SMEM_TOTAL>>>(
            H16, nullptr, Xres, Xt16, b[2 * br + 1], 2 * br + 1, 1, 1);
    }

    transpose_out_kernel<<<dim3(LSEQ / 32, CCH / 32, NB), dim3(32, 8)>>>(Xres, (float*)d_out);
}